// round 14
// baseline (speedup 1.0000x reference)
#include <cuda_runtime.h>
#include <cuda_fp16.h>
#include <stdint.h>

#define NN   50000
#define EE   800000
#define FIN  512
#define HH   256
#define OUTF 2
#define BN_EPS 1e-5f
#define SCB  98          // scan blocks: ceil(NN/512)

// -------------------- scratch --------------------
__device__ int    g_is64;
__device__ float  g_deg[NN];
__device__ float  g_dinv[NN];
__device__ float  g_snorm[NN];
__device__ __half g_h16[(size_t)NN * HH];
__device__ float  g_h3[(size_t)NN * OUTF];
__device__ __half g_hi[(size_t)NN * HH];
__device__ __half g_Wh1[(size_t)HH * FIN];
__device__ __half g_Wh2[(size_t)HH * HH];
// CSR (by destination col)
__device__ int    g_cnt[NN];
__device__ int    g_rowptr[NN + 1];
__device__ int    g_fill[NN];
__device__ int    g_src[EE];
__device__ float  g_wedge[EE];
// chained-scan state
__device__ volatile int g_scan_ready[SCB];   // 1 when g_scan_pref[b] valid
__device__ int          g_scan_pref[SCB];    // inclusive running totals

// -------------------- branch A: W1 transpose --------------------
__global__ void k_preW1(const float* __restrict__ W1, __half* __restrict__ Wh1) {
    int u = blockIdx.x * 256 + threadIdx.x;          // 512 blocks
    int nn = u >> 9, k = u & 511;
    Wh1[u] = __float2half_rn(W1[(size_t)k * 256 + nn]);
}
// -------------------- branch B: W2 transpose --------------------
__global__ void k_preW2(const float* __restrict__ W2, __half* __restrict__ Wh2) {
    int u = blockIdx.x * 256 + threadIdx.x;          // 256 blocks
    int nn = u >> 8, k = u & 255;
    Wh2[u] = __float2half_rn(W2[(size_t)k * 256 + nn]);
}

// -------------------- branch B: init + dtype detect + scan reset --------------------
__global__ void k_preG(const unsigned int* __restrict__ wr,
                       float* __restrict__ deg, int* __restrict__ cnt,
                       int* __restrict__ fill, int n) {
    int i = blockIdx.x * blockDim.x + threadIdx.x;
    if (i < n) { deg[i] = 1.0f; cnt[i] = 0; fill[i] = 0; }
    if (i < SCB) g_scan_ready[i] = 0;
    if (blockIdx.x == 0) {
        int ok = 1;
        for (int j = threadIdx.x; j < 2048; j += 256)
            if (wr[2 * j + 1] != 0u) ok = 0;
        int all = __syncthreads_and(ok);
        if (threadIdx.x == 0) g_is64 = all;
    }
}

__global__ void k_extract_deg(const unsigned int* __restrict__ wr,
                              const float* __restrict__ w,
                              float* __restrict__ deg, int* __restrict__ cnt, int E) {
    int e = blockIdx.x * blockDim.x + threadIdx.x;
    if (e >= E) return;
    int c;
    if (g_is64) c = (int)wr[2 * (E + e)];
    else        c = (int)wr[E + e];
    atomicAdd(&deg[c], w[e]);
    atomicAdd(&cnt[c], 1);
}

// single-pass chained scan: rowptr (exclusive) + dinv/snorm
__global__ void __launch_bounds__(512)
k_scanF(const int* __restrict__ cnt, int* __restrict__ rowptr,
        const float* __restrict__ deg, float* __restrict__ dinv,
        float* __restrict__ snorm, int n, int E) {
    __shared__ int sh[512];
    __shared__ int base_sh;
    int t = threadIdx.x;
    int b = blockIdx.x;
    int i = b * 512 + t;
    int v = (i < n) ? cnt[i] : 0;
    sh[t] = v;
    __syncthreads();
#pragma unroll
    for (int off = 1; off < 512; off <<= 1) {
        int x = (t >= off) ? sh[t - off] : 0;
        __syncthreads();
        sh[t] += x;
        __syncthreads();
    }
    // chain: publish inclusive running total, consume predecessor's
    if (t == 0) {
        int prev = 0;
        if (b > 0) {
            while (g_scan_ready[b - 1] == 0) { }   // all SCB blocks co-resident
            __threadfence();
            prev = g_scan_pref[b - 1];
        }
        g_scan_pref[b] = prev + sh[511];
        __threadfence();
        g_scan_ready[b] = 1;
        base_sh = prev;
    }
    __syncthreads();
    int base = base_sh;
    if (i < n) {
        rowptr[i] = base + sh[t] - v;   // exclusive
        float d = rsqrtf(deg[i]);
        dinv[i] = d;
        snorm[i] = d * d;
    }
    if (i == 0) rowptr[n] = E;
}

__global__ void k_norm_fill(const unsigned int* __restrict__ wr,
                            const float* __restrict__ w, const float* __restrict__ dinv,
                            const int* __restrict__ rowptr, int* __restrict__ fill,
                            int* __restrict__ src, float* __restrict__ wedge, int E) {
    int e = blockIdx.x * blockDim.x + threadIdx.x;
    if (e >= E) return;
    int r, c;
    if (g_is64) { r = (int)wr[2 * e]; c = (int)wr[2 * (E + e)]; }
    else        { r = (int)wr[e];     c = (int)wr[E + e]; }
    float nv = dinv[r] * w[e] * dinv[c];
    int p = rowptr[c] + atomicAdd(&fill[c], 1);
    src[p] = r;
    wedge[p] = nv;
}

// -------------------- helpers --------------------
__device__ __forceinline__ uint32_t pack2h(__half a, __half b) {
    __half2 p = __halves2half2(a, b);
    return *reinterpret_cast<uint32_t*>(&p);
}
__device__ __forceinline__ void h8_to_f8(uint4 raw, float* f) {
    __half2* p = reinterpret_cast<__half2*>(&raw);
#pragma unroll
    for (int j = 0; j < 4; j++) {
        float2 t = __half22float2(p[j]);
        f[2 * j] = t.x;
        f[2 * j + 1] = t.y;
    }
}

__device__ __forceinline__ void mma16816(float* d, const uint32_t* a, const uint32_t* b) {
    asm volatile(
        "mma.sync.aligned.m16n8k16.row.col.f32.f16.f16.f32 "
        "{%0,%1,%2,%3}, {%4,%5,%6,%7}, {%8,%9}, {%0,%1,%2,%3};"
        : "+f"(d[0]), "+f"(d[1]), "+f"(d[2]), "+f"(d[3])
        : "r"(a[0]), "r"(a[1]), "r"(a[2]), "r"(a[3]), "r"(b[0]), "r"(b[1]));
}
__device__ __forceinline__ void ldmatrix_x4(uint32_t& r0, uint32_t& r1, uint32_t& r2,
                                            uint32_t& r3, uint32_t saddr) {
    asm volatile("ldmatrix.sync.aligned.m8n8.x4.shared.b16 {%0,%1,%2,%3}, [%4];"
                 : "=r"(r0), "=r"(r1), "=r"(r2), "=r"(r3) : "r"(saddr));
}
__device__ __forceinline__ void cp_async16(uint32_t saddr, const void* gaddr, int src_sz) {
    asm volatile("cp.async.cg.shared.global [%0], [%1], 16, %2;"
                 :: "r"(saddr), "l"(gaddr), "r"(src_sz));
}
__device__ __forceinline__ void cp_commit() { asm volatile("cp.async.commit_group;"); }
__device__ __forceinline__ void cp_wait1()  { asm volatile("cp.async.wait_group 1;"); }
__device__ __forceinline__ void cp_wait0()  { asm volatile("cp.async.wait_group 0;"); }

// -------------------- single-term fp16 HMMA GEMM, BM=64/BN=256, occ 2 --------------------
template <int K, bool AFP32>
__global__ __launch_bounds__(256, 2)
void mma_gemm(const float* __restrict__ Af, const __half* __restrict__ Ahalf,
              const __half* __restrict__ Bh,
              __half* __restrict__ C, int Nr) {
    constexpr int NCH = K / 32;
    extern __shared__ char smem[];
    uint32_t* Bs = reinterpret_cast<uint32_t*>(smem);
    uint32_t* Ah = reinterpret_cast<uint32_t*>(smem + 40960);

    const int tid  = threadIdx.x;
    const int lane = tid & 31;
    const int wid  = tid >> 5;
    const int warp_m = wid & 1;
    const int warp_n = wid >> 1;
    const int bm = blockIdx.x * 64;

    float acc[2][8][4];
#pragma unroll
    for (int mt = 0; mt < 2; mt++)
#pragma unroll
        for (int nt = 0; nt < 8; nt++)
#pragma unroll
            for (int q = 0; q < 4; q++) acc[mt][nt][q] = 0.0f;

    float4 fa[2];

    auto loadAf = [&](int q) {
        const int kt = q * 32;
        int r = tid >> 2, k8 = tid & 3;
        int gr = bm + r;
        if (gr < Nr) {
            const float4* p = reinterpret_cast<const float4*>(
                Af + (size_t)gr * K + kt + k8 * 8);
            fa[0] = p[0];
            fa[1] = p[1];
        } else {
            fa[0] = make_float4(0.f, 0.f, 0.f, 0.f);
            fa[1] = make_float4(0.f, 0.f, 0.f, 0.f);
        }
    };
    auto storeA = [&](int st) {
        int r = tid >> 2, k8 = tid & 3;
        uint32_t hw[4];
        hw[0] = pack2h(__float2half_rn(fa[0].x), __float2half_rn(fa[0].y));
        hw[1] = pack2h(__float2half_rn(fa[0].z), __float2half_rn(fa[0].w));
        hw[2] = pack2h(__float2half_rn(fa[1].x), __float2half_rn(fa[1].y));
        hw[3] = pack2h(__float2half_rn(fa[1].z), __float2half_rn(fa[1].w));
        int woff = st * 1280 + r * 20 + k8 * 4;
        *reinterpret_cast<uint4*>(&Ah[woff]) = make_uint4(hw[0], hw[1], hw[2], hw[3]);
    };
    auto asyncA16 = [&](int st, int q) {
        const int kt = q * 32;
        int r = tid >> 2, k8 = tid & 3;
        int gr = bm + r;
        int ok = (gr < Nr);
        size_t srcoff = (size_t)(ok ? gr : 0) * K + kt + k8 * 8;
        int woff = st * 1280 + r * 20 + k8 * 4;
        cp_async16((uint32_t)__cvta_generic_to_shared(&Ah[woff]), Ahalf + srcoff, ok ? 16 : 0);
    };
    auto asyncB = [&](int st, int q) {
        const int kt = q * 32;
#pragma unroll
        for (int i = 0; i < 4; i++) {
            int u = tid + i * 256;
            int r = u >> 2, k8 = u & 3;
            int woff = st * 5120 + r * 20 + k8 * 4;
            cp_async16((uint32_t)__cvta_generic_to_shared(&Bs[woff]),
                       Bh + (size_t)r * K + kt + k8 * 8, 16);
        }
    };

    const int aRow  = warp_m * 32 + (lane & 7) + ((lane >> 3) & 1) * 8;
    const int aWsel = (lane >> 4) * 4;
    const int bRow  = warp_n * 64 + (lane & 7) + (lane >> 4) * 8;
    const int bWsel = ((lane >> 3) & 1) * 4;

    auto compute = [&](int st) {
#pragma unroll
        for (int ks = 0; ks < 2; ks++) {
            const int kw = ks * 8;
            uint32_t a[2][4], b[8][2];
#pragma unroll
            for (int mt = 0; mt < 2; mt++) {
                uint32_t ad = (uint32_t)__cvta_generic_to_shared(
                    &Ah[st * 1280 + (aRow + mt * 16) * 20 + kw + aWsel]);
                ldmatrix_x4(a[mt][0], a[mt][1], a[mt][2], a[mt][3], ad);
            }
#pragma unroll
            for (int np = 0; np < 4; np++) {
                uint32_t bd = (uint32_t)__cvta_generic_to_shared(
                    &Bs[st * 5120 + (bRow + np * 16) * 20 + kw + bWsel]);
                ldmatrix_x4(b[2 * np][0], b[2 * np][1], b[2 * np + 1][0], b[2 * np + 1][1], bd);
            }
#pragma unroll
            for (int mt = 0; mt < 2; mt++)
#pragma unroll
                for (int nt = 0; nt < 8; nt++)
                    mma16816(acc[mt][nt], a[mt], b[nt]);
        }
    };

    if (AFP32) loadAf(0); else asyncA16(0, 0);
    asyncB(0, 0);
    cp_commit();
    if (AFP32) storeA(0);

    for (int q = 0; q < NCH; q++) {
        if (q + 1 < NCH) {
            if (AFP32) loadAf(q + 1); else asyncA16((q + 1) & 1, q + 1);
            asyncB((q + 1) & 1, q + 1);
            cp_commit();
            cp_wait1();
        } else {
            cp_wait0();
        }
        __syncthreads();
        compute(q & 1);
        if (AFP32 && q + 1 < NCH) storeA((q + 1) & 1);
        __syncthreads();
    }

    const int lr4 = lane >> 2, lk = lane & 3;
#pragma unroll
    for (int mt = 0; mt < 2; mt++) {
#pragma unroll
        for (int half = 0; half < 2; half++) {
            int r = bm + warp_m * 32 + mt * 16 + half * 8 + lr4;
            if (r >= Nr) continue;
#pragma unroll
            for (int nt = 0; nt < 8; nt++) {
                int c = warp_n * 64 + nt * 8 + lk * 2;
                *reinterpret_cast<__half2*>(C + (size_t)r * 256 + c) =
                    __floats2half2_rn(acc[mt][nt][half * 2], acc[mt][nt][half * 2 + 1]);
            }
        }
    }
}

// -------------------- fused gather + BN + ReLU (warp per node, unroll x4) --------------------
template <bool W3MODE>
__global__ __launch_bounds__(256)
void k_gather_bn(const __half* __restrict__ h,
                 const int* __restrict__ rowptr, const int* __restrict__ src,
                 const float* __restrict__ wedge, const float* __restrict__ snorm,
                 const float* __restrict__ bb, const float* __restrict__ gg,
                 const float* __restrict__ bee, const float* __restrict__ mm,
                 const float* __restrict__ vv,
                 __half* __restrict__ hnext,
                 const float* __restrict__ W3, float* __restrict__ h3, int n) {
    int i = blockIdx.x * 8 + (threadIdx.x >> 5);
    int lane = threadIdx.x & 31;
    int c = lane * 8;

    float acc[8], f[8];
    h8_to_f8(*reinterpret_cast<const uint4*>(h + (size_t)i * HH + c), f);
    float s = snorm[i];
#pragma unroll
    for (int j = 0; j < 8; j++) acc[j] = f[j] * s;

    int p   = rowptr[i];
    int end = rowptr[i + 1];
    for (; p + 3 < end; p += 4) {
        int   r0 = __ldg(&src[p]),     r1 = __ldg(&src[p + 1]);
        int   r2 = __ldg(&src[p + 2]), r3 = __ldg(&src[p + 3]);
        float w0 = __ldg(&wedge[p]),     w1 = __ldg(&wedge[p + 1]);
        float w2 = __ldg(&wedge[p + 2]), w3 = __ldg(&wedge[p + 3]);
        uint4 q0 = *reinterpret_cast<const uint4*>(h + (size_t)r0 * HH + c);
        uint4 q1 = *reinterpret_cast<const uint4*>(h + (size_t)r1 * HH + c);
        uint4 q2 = *reinterpret_cast<const uint4*>(h + (size_t)r2 * HH + c);
        uint4 q3 = *reinterpret_cast<const uint4*>(h + (size_t)r3 * HH + c);
        float f0[8], f1[8], f2[8], f3[8];
        h8_to_f8(q0, f0); h8_to_f8(q1, f1); h8_to_f8(q2, f2); h8_to_f8(q3, f3);
#pragma unroll
        for (int j = 0; j < 8; j++)
            acc[j] += w0 * f0[j] + w1 * f1[j] + w2 * f2[j] + w3 * f3[j];
    }
    for (; p < end; p++) {
        int r = __ldg(&src[p]);
        float wv = __ldg(&wedge[p]);
        float f0[8];
        h8_to_f8(*reinterpret_cast<const uint4*>(h + (size_t)r * HH + c), f0);
#pragma unroll
        for (int j = 0; j < 8; j++) acc[j] += wv * f0[j];
    }

    float o[8];
#pragma unroll
    for (int halfp = 0; halfp < 2; halfp++) {
        int cc = c + halfp * 4;
        float4 B  = *reinterpret_cast<const float4*>(bb + cc);
        float4 G  = *reinterpret_cast<const float4*>(gg + cc);
        float4 BE = *reinterpret_cast<const float4*>(bee + cc);
        float4 M  = *reinterpret_cast<const float4*>(mm + cc);
        float4 V  = *reinterpret_cast<const float4*>(vv + cc);
        float* op = o + halfp * 4;
        float* ap = acc + halfp * 4;
        op[0] = fmaxf((ap[0] + B.x - M.x) * rsqrtf(V.x + BN_EPS) * G.x + BE.x, 0.0f);
        op[1] = fmaxf((ap[1] + B.y - M.y) * rsqrtf(V.y + BN_EPS) * G.y + BE.y, 0.0f);
        op[2] = fmaxf((ap[2] + B.z - M.z) * rsqrtf(V.z + BN_EPS) * G.z + BE.z, 0.0f);
        op[3] = fmaxf((ap[3] + B.w - M.w) * rsqrtf(V.w + BN_EPS) * G.w + BE.w, 0.0f);
    }

    if (!W3MODE) {
        uint32_t hw[4];
#pragma unroll
        for (int j = 0; j < 4; j++) {
            __half2 hp = __floats2half2_rn(o[2 * j], o[2 * j + 1]);
            hw[j] = *reinterpret_cast<uint32_t*>(&hp);
        }
        *reinterpret_cast<uint4*>(hnext + (size_t)i * HH + c) =
            make_uint4(hw[0], hw[1], hw[2], hw[3]);
    } else {
        float p0 = 0.f, p1 = 0.f;
#pragma unroll
        for (int j = 0; j < 8; j++) {
            p0 += o[j] * __ldg(&W3[(c + j) * 2]);
            p1 += o[j] * __ldg(&W3[(c + j) * 2 + 1]);
        }
#pragma unroll
        for (int off = 16; off; off >>= 1) {
            p0 += __shfl_xor_sync(0xFFFFFFFFu, p0, off);
            p1 += __shfl_xor_sync(0xFFFFFFFFu, p1, off);
        }
        if (lane == 0) {
            h3[2 * i]     = p0;
            h3[2 * i + 1] = p1;
        }
    }
}

// -------------------- final gather (OUT=2) --------------------
__global__ void k_gather_out(const float* __restrict__ h3,
                             const int* __restrict__ rowptr, const int* __restrict__ src,
                             const float* __restrict__ wedge, const float* __restrict__ snorm,
                             const float* __restrict__ b3, float* __restrict__ out, int n) {
    int i = blockIdx.x * blockDim.x + threadIdx.x;
    if (i >= n) return;
    float s = snorm[i];
    float a0 = s * h3[2 * i]     + b3[0];
    float a1 = s * h3[2 * i + 1] + b3[1];
    int p = rowptr[i], end = rowptr[i + 1];
    for (; p + 1 < end; p += 2) {
        int   r0 = __ldg(&src[p]),   r1 = __ldg(&src[p + 1]);
        float w0 = __ldg(&wedge[p]), w1 = __ldg(&wedge[p + 1]);
        a0 += w0 * h3[2 * r0]     + w1 * h3[2 * r1];
        a1 += w0 * h3[2 * r0 + 1] + w1 * h3[2 * r1 + 1];
    }
    if (p < end) {
        int r = __ldg(&src[p]);
        float wv = __ldg(&wedge[p]);
        a0 += wv * h3[2 * r];
        a1 += wv * h3[2 * r + 1];
    }
    out[2 * i]     = a0;
    out[2 * i + 1] = a1;
}

// -------------------- launch --------------------
extern "C" void kernel_launch(void* const* d_in, const int* in_sizes, int n_in,
                              void* d_out, int out_size) {
    const float*        x   = (const float*)d_in[0];
    const unsigned int* eiw = (const unsigned int*)d_in[1];
    const float*        w   = (const float*)d_in[2];
    const float*        W1  = (const float*)d_in[3];
    const float*        b1  = (const float*)d_in[4];
    const float*        g1  = (const float*)d_in[5];
    const float*        be1 = (const float*)d_in[6];
    const float*        m1  = (const float*)d_in[7];
    const float*        v1  = (const float*)d_in[8];
    const float*        W2  = (const float*)d_in[9];
    const float*        b2  = (const float*)d_in[10];
    const float*        g2  = (const float*)d_in[11];
    const float*        be2 = (const float*)d_in[12];
    const float*        m2  = (const float*)d_in[13];
    const float*        v2  = (const float*)d_in[14];
    const float*        W3  = (const float*)d_in[15];
    const float*        b3  = (const float*)d_in[16];
    float* out = (float*)d_out;

    int *cnt, *rowptr, *fill, *src;
    float *deg, *dinv, *snorm, *h3, *wedge;
    __half *h16, *hi, *Wh1, *Wh2;
    cudaGetSymbolAddress((void**)&cnt,    g_cnt);
    cudaGetSymbolAddress((void**)&rowptr, g_rowptr);
    cudaGetSymbolAddress((void**)&fill,   g_fill);
    cudaGetSymbolAddress((void**)&src,    g_src);
    cudaGetSymbolAddress((void**)&wedge,  g_wedge);
    cudaGetSymbolAddress((void**)&deg,    g_deg);
    cudaGetSymbolAddress((void**)&dinv,   g_dinv);
    cudaGetSymbolAddress((void**)&snorm,  g_snorm);
    cudaGetSymbolAddress((void**)&h16,    g_h16);
    cudaGetSymbolAddress((void**)&h3,     g_h3);
    cudaGetSymbolAddress((void**)&hi,     g_hi);
    cudaGetSymbolAddress((void**)&Wh1,    g_Wh1);
    cudaGetSymbolAddress((void**)&Wh2,    g_Wh2);

    static cudaStream_t sB = nullptr;
    static cudaEvent_t  evF = nullptr, evJ = nullptr;
    if (sB == nullptr) {
        cudaStreamCreateWithFlags(&sB, cudaStreamNonBlocking);
        cudaEventCreateWithFlags(&evF, cudaEventDisableTiming);
        cudaEventCreateWithFlags(&evJ, cudaEventDisableTiming);
    }

    const int n = NN, E = EE;
    const int SMEM = 51200;
    cudaFuncSetAttribute(mma_gemm<FIN, true>,
                         cudaFuncAttributeMaxDynamicSharedMemorySize, SMEM);
    cudaFuncSetAttribute(mma_gemm<HH, false>,
                         cudaFuncAttributeMaxDynamicSharedMemorySize, SMEM);

    dim3 t256(256);
    int nb_n  = (n + 255) / 256;
    int nb_e  = (E + 255) / 256;
    int nb_g  = n / 8;                 // 6250
    int gemm_grid = (n + 63) / 64;     // 782

    // ---- fork: branch B (graph preproc + W2 transpose) on sB ----
    cudaEventRecord(evF, 0);
    cudaStreamWaitEvent(sB, evF, 0);
    k_preG<<<nb_n, t256, 0, sB>>>(eiw, deg, cnt, fill, n);
    k_extract_deg<<<nb_e, t256, 0, sB>>>(eiw, w, deg, cnt, E);
    k_scanF<<<SCB, 512, 0, sB>>>(cnt, rowptr, deg, dinv, snorm, n, E);
    k_norm_fill<<<nb_e, t256, 0, sB>>>(eiw, w, dinv, rowptr, fill, src, wedge, E);
    k_preW2<<<256, t256, 0, sB>>>(W2, Wh2);
    cudaEventRecord(evJ, sB);

    // ---- branch A (W1 + GEMM1) on default stream ----
    k_preW1<<<512, t256>>>(W1, Wh1);
    mma_gemm<FIN, true><<<gemm_grid, t256, SMEM>>>(x, nullptr, Wh1, h16, n);

    // ---- join ----
    cudaStreamWaitEvent(0, evJ, 0);

    // ---- layer 1 gather ----
    k_gather_bn<false><<<nb_g, t256>>>(h16, rowptr, src, wedge, snorm,
                                       b1, g1, be1, m1, v1, hi, nullptr, nullptr, n);

    // ---- layer 2 (A fp16, +W3 fused) ----
    mma_gemm<HH, false><<<gemm_grid, t256, SMEM>>>(nullptr, hi, Wh2, h16, n);
    k_gather_bn<true><<<nb_g, t256>>>(h16, rowptr, src, wedge, snorm,
                                      b2, g2, be2, m2, v2, nullptr, W3, h3, n);

    // ---- layer 3 ----
    k_gather_out<<<nb_n, t256>>>(h3, rowptr, src, wedge, snorm, b3, out, n);
}

// round 15
// speedup vs baseline: 1.3828x; 1.3828x over previous
#include <cuda_runtime.h>
#include <cuda_fp16.h>
#include <stdint.h>

#define NN   50000
#define EE   800000
#define FIN  512
#define HH   256
#define OUTF 2
#define BN_EPS 1e-5f

// -------------------- scratch --------------------
__device__ int    g_is64;
__device__ int    g_row[EE];
__device__ int    g_col[EE];
__device__ float  g_deg[NN];
__device__ float  g_dinv[NN];
__device__ float  g_snorm[NN];
__device__ __half g_h16[(size_t)NN * HH];
__device__ float  g_h3[(size_t)NN * OUTF];
__device__ __half g_hi[(size_t)NN * HH];
__device__ __half g_Wh1[(size_t)HH * FIN];
__device__ __half g_Wh2[(size_t)HH * HH];
// CSR (by destination col)
__device__ int    g_cnt[NN];
__device__ int    g_incl[NN];
__device__ int    g_blksum[128];
__device__ int    g_rowptr[NN + 1];
__device__ int    g_fill[NN];
__device__ int    g_src[EE];
__device__ float  g_wedge[EE];

// -------------------- branch A: W1 transpose --------------------
__global__ void k_preW1(const float* __restrict__ W1, __half* __restrict__ Wh1) {
    int u = blockIdx.x * 256 + threadIdx.x;          // 512 blocks
    int nn = u >> 9, k = u & 511;
    Wh1[u] = __float2half_rn(W1[(size_t)k * 256 + nn]);
}
// -------------------- branch B: W2 transpose --------------------
__global__ void k_preW2(const float* __restrict__ W2, __half* __restrict__ Wh2) {
    int u = blockIdx.x * 256 + threadIdx.x;          // 256 blocks
    int nn = u >> 8, k = u & 255;
    Wh2[u] = __float2half_rn(W2[(size_t)k * 256 + nn]);
}

// -------------------- branch B: graph preprocessing --------------------
__global__ void k_preG(const unsigned int* __restrict__ wr,
                       float* __restrict__ deg, int* __restrict__ cnt,
                       int* __restrict__ fill, int n) {
    int i = blockIdx.x * blockDim.x + threadIdx.x;
    if (i < n) { deg[i] = 1.0f; cnt[i] = 0; fill[i] = 0; }
    if (blockIdx.x == 0) {
        int ok = 1;
        for (int j = threadIdx.x; j < 2048; j += 256)
            if (wr[2 * j + 1] != 0u) ok = 0;
        int all = __syncthreads_and(ok);
        if (threadIdx.x == 0) g_is64 = all;
    }
}

__global__ void k_extract_deg(const unsigned int* __restrict__ wr,
                              const float* __restrict__ w,
                              int* __restrict__ row, int* __restrict__ col,
                              float* __restrict__ deg, int* __restrict__ cnt, int E) {
    int e = blockIdx.x * blockDim.x + threadIdx.x;
    if (e >= E) return;
    int r, c;
    if (g_is64) { r = (int)wr[2 * e]; c = (int)wr[2 * (E + e)]; }
    else        { r = (int)wr[e];     c = (int)wr[E + e]; }
    row[e] = r;
    col[e] = c;
    atomicAdd(&deg[c], w[e]);
    atomicAdd(&cnt[c], 1);
}

__global__ void k_scan1(const int* __restrict__ cnt, int* __restrict__ incl,
                        int* __restrict__ blksum, int n) {
    __shared__ int sh[512];
    int t = threadIdx.x;
    int i = blockIdx.x * 512 + t;
    int v = (i < n) ? cnt[i] : 0;
    sh[t] = v;
    __syncthreads();
#pragma unroll
    for (int off = 1; off < 512; off <<= 1) {
        int x = (t >= off) ? sh[t - off] : 0;
        __syncthreads();
        sh[t] += x;
        __syncthreads();
    }
    if (i < n) incl[i] = sh[t];
    if (t == 511) blksum[blockIdx.x] = sh[511];
}

__global__ void k_scan23(const int* __restrict__ incl, const int* __restrict__ cnt,
                         const int* __restrict__ blksum, int* __restrict__ rowptr,
                         const float* __restrict__ deg, float* __restrict__ dinv,
                         float* __restrict__ snorm, int n, int E, int nb) {
    __shared__ int sh[128];
    int t = threadIdx.x;
    if (t < 128) sh[t] = (t < nb) ? blksum[t] : 0;
    __syncthreads();
#pragma unroll
    for (int off = 1; off < 128; off <<= 1) {
        int x = 0;
        if (t < 128 && t >= off) x = sh[t - off];
        __syncthreads();
        if (t < 128) sh[t] += x;
        __syncthreads();
    }
    int i = blockIdx.x * blockDim.x + t;
    if (i < n) {
        int blk = i / 512;
        int exoff = sh[blk] - blksum[blk];
        rowptr[i] = incl[i] - cnt[i] + exoff;
        float d = rsqrtf(deg[i]);
        dinv[i] = d;
        snorm[i] = d * d;
    }
    if (i == 0) rowptr[n] = E;
}

__global__ void k_norm_fill(const int* __restrict__ row, const int* __restrict__ col,
                            const float* __restrict__ w, const float* __restrict__ dinv,
                            const int* __restrict__ rowptr, int* __restrict__ fill,
                            int* __restrict__ src, float* __restrict__ wedge, int E) {
    int e = blockIdx.x * blockDim.x + threadIdx.x;
    if (e >= E) return;
    int r = row[e], c = col[e];
    float nv = dinv[r] * w[e] * dinv[c];
    int p = rowptr[c] + atomicAdd(&fill[c], 1);
    src[p] = r;
    wedge[p] = nv;
}

// -------------------- helpers --------------------
__device__ __forceinline__ uint32_t pack2h(__half a, __half b) {
    __half2 p = __halves2half2(a, b);
    return *reinterpret_cast<uint32_t*>(&p);
}
__device__ __forceinline__ void h8_to_f8(uint4 raw, float* f) {
    __half2* p = reinterpret_cast<__half2*>(&raw);
#pragma unroll
    for (int j = 0; j < 4; j++) {
        float2 t = __half22float2(p[j]);
        f[2 * j] = t.x;
        f[2 * j + 1] = t.y;
    }
}

__device__ __forceinline__ void mma16816(float* d, const uint32_t* a, const uint32_t* b) {
    asm volatile(
        "mma.sync.aligned.m16n8k16.row.col.f32.f16.f16.f32 "
        "{%0,%1,%2,%3}, {%4,%5,%6,%7}, {%8,%9}, {%0,%1,%2,%3};"
        : "+f"(d[0]), "+f"(d[1]), "+f"(d[2]), "+f"(d[3])
        : "r"(a[0]), "r"(a[1]), "r"(a[2]), "r"(a[3]), "r"(b[0]), "r"(b[1]));
}
__device__ __forceinline__ void ldmatrix_x4(uint32_t& r0, uint32_t& r1, uint32_t& r2,
                                            uint32_t& r3, uint32_t saddr) {
    asm volatile("ldmatrix.sync.aligned.m8n8.x4.shared.b16 {%0,%1,%2,%3}, [%4];"
                 : "=r"(r0), "=r"(r1), "=r"(r2), "=r"(r3) : "r"(saddr));
}
__device__ __forceinline__ void cp_async16(uint32_t saddr, const void* gaddr, int src_sz) {
    asm volatile("cp.async.cg.shared.global [%0], [%1], 16, %2;"
                 :: "r"(saddr), "l"(gaddr), "r"(src_sz));
}
__device__ __forceinline__ void cp_commit() { asm volatile("cp.async.commit_group;"); }
__device__ __forceinline__ void cp_wait1()  { asm volatile("cp.async.wait_group 1;"); }
__device__ __forceinline__ void cp_wait0()  { asm volatile("cp.async.wait_group 0;"); }

// -------------------- single-term fp16 HMMA GEMM, BM=64/BN=256, occ 2 --------------------
template <int K, bool AFP32>
__global__ __launch_bounds__(256, 2)
void mma_gemm(const float* __restrict__ Af, const __half* __restrict__ Ahalf,
              const __half* __restrict__ Bh,
              __half* __restrict__ C, int Nr) {
    constexpr int NCH = K / 32;
    extern __shared__ char smem[];
    uint32_t* Bs = reinterpret_cast<uint32_t*>(smem);
    uint32_t* Ah = reinterpret_cast<uint32_t*>(smem + 40960);

    const int tid  = threadIdx.x;
    const int lane = tid & 31;
    const int wid  = tid >> 5;
    const int warp_m = wid & 1;
    const int warp_n = wid >> 1;
    const int bm = blockIdx.x * 64;

    float acc[2][8][4];
#pragma unroll
    for (int mt = 0; mt < 2; mt++)
#pragma unroll
        for (int nt = 0; nt < 8; nt++)
#pragma unroll
            for (int q = 0; q < 4; q++) acc[mt][nt][q] = 0.0f;

    float4 fa[2];

    auto loadAf = [&](int q) {
        const int kt = q * 32;
        int r = tid >> 2, k8 = tid & 3;
        int gr = bm + r;
        if (gr < Nr) {
            const float4* p = reinterpret_cast<const float4*>(
                Af + (size_t)gr * K + kt + k8 * 8);
            fa[0] = p[0];
            fa[1] = p[1];
        } else {
            fa[0] = make_float4(0.f, 0.f, 0.f, 0.f);
            fa[1] = make_float4(0.f, 0.f, 0.f, 0.f);
        }
    };
    auto storeA = [&](int st) {
        int r = tid >> 2, k8 = tid & 3;
        uint32_t hw[4];
        hw[0] = pack2h(__float2half_rn(fa[0].x), __float2half_rn(fa[0].y));
        hw[1] = pack2h(__float2half_rn(fa[0].z), __float2half_rn(fa[0].w));
        hw[2] = pack2h(__float2half_rn(fa[1].x), __float2half_rn(fa[1].y));
        hw[3] = pack2h(__float2half_rn(fa[1].z), __float2half_rn(fa[1].w));
        int woff = st * 1280 + r * 20 + k8 * 4;
        *reinterpret_cast<uint4*>(&Ah[woff]) = make_uint4(hw[0], hw[1], hw[2], hw[3]);
    };
    auto asyncA16 = [&](int st, int q) {
        const int kt = q * 32;
        int r = tid >> 2, k8 = tid & 3;
        int gr = bm + r;
        int ok = (gr < Nr);
        size_t srcoff = (size_t)(ok ? gr : 0) * K + kt + k8 * 8;
        int woff = st * 1280 + r * 20 + k8 * 4;
        cp_async16((uint32_t)__cvta_generic_to_shared(&Ah[woff]), Ahalf + srcoff, ok ? 16 : 0);
    };
    auto asyncB = [&](int st, int q) {
        const int kt = q * 32;
#pragma unroll
        for (int i = 0; i < 4; i++) {
            int u = tid + i * 256;
            int r = u >> 2, k8 = u & 3;
            int woff = st * 5120 + r * 20 + k8 * 4;
            cp_async16((uint32_t)__cvta_generic_to_shared(&Bs[woff]),
                       Bh + (size_t)r * K + kt + k8 * 8, 16);
        }
    };

    const int aRow  = warp_m * 32 + (lane & 7) + ((lane >> 3) & 1) * 8;
    const int aWsel = (lane >> 4) * 4;
    const int bRow  = warp_n * 64 + (lane & 7) + (lane >> 4) * 8;
    const int bWsel = ((lane >> 3) & 1) * 4;

    auto compute = [&](int st) {
#pragma unroll
        for (int ks = 0; ks < 2; ks++) {
            const int kw = ks * 8;
            uint32_t a[2][4], b[8][2];
#pragma unroll
            for (int mt = 0; mt < 2; mt++) {
                uint32_t ad = (uint32_t)__cvta_generic_to_shared(
                    &Ah[st * 1280 + (aRow + mt * 16) * 20 + kw + aWsel]);
                ldmatrix_x4(a[mt][0], a[mt][1], a[mt][2], a[mt][3], ad);
            }
#pragma unroll
            for (int np = 0; np < 4; np++) {
                uint32_t bd = (uint32_t)__cvta_generic_to_shared(
                    &Bs[st * 5120 + (bRow + np * 16) * 20 + kw + bWsel]);
                ldmatrix_x4(b[2 * np][0], b[2 * np][1], b[2 * np + 1][0], b[2 * np + 1][1], bd);
            }
#pragma unroll
            for (int mt = 0; mt < 2; mt++)
#pragma unroll
                for (int nt = 0; nt < 8; nt++)
                    mma16816(acc[mt][nt], a[mt], b[nt]);
        }
    };

    if (AFP32) loadAf(0); else asyncA16(0, 0);
    asyncB(0, 0);
    cp_commit();
    if (AFP32) storeA(0);

    for (int q = 0; q < NCH; q++) {
        if (q + 1 < NCH) {
            if (AFP32) loadAf(q + 1); else asyncA16((q + 1) & 1, q + 1);
            asyncB((q + 1) & 1, q + 1);
            cp_commit();
            cp_wait1();
        } else {
            cp_wait0();
        }
        __syncthreads();
        compute(q & 1);
        if (AFP32 && q + 1 < NCH) storeA((q + 1) & 1);
        __syncthreads();
    }

    const int lr4 = lane >> 2, lk = lane & 3;
#pragma unroll
    for (int mt = 0; mt < 2; mt++) {
#pragma unroll
        for (int half = 0; half < 2; half++) {
            int r = bm + warp_m * 32 + mt * 16 + half * 8 + lr4;
            if (r >= Nr) continue;
#pragma unroll
            for (int nt = 0; nt < 8; nt++) {
                int c = warp_n * 64 + nt * 8 + lk * 2;
                *reinterpret_cast<__half2*>(C + (size_t)r * 256 + c) =
                    __floats2half2_rn(acc[mt][nt][half * 2], acc[mt][nt][half * 2 + 1]);
            }
        }
    }
}

// -------------------- fused gather + BN + ReLU (warp per node, unroll x4) --------------------
template <bool W3MODE>
__global__ __launch_bounds__(256)
void k_gather_bn(const __half* __restrict__ h,
                 const int* __restrict__ rowptr, const int* __restrict__ src,
                 const float* __restrict__ wedge, const float* __restrict__ snorm,
                 const float* __restrict__ bb, const float* __restrict__ gg,
                 const float* __restrict__ bee, const float* __restrict__ mm,
                 const float* __restrict__ vv,
                 __half* __restrict__ hnext,
                 const float* __restrict__ W3, float* __restrict__ h3, int n) {
    int i = blockIdx.x * 8 + (threadIdx.x >> 5);
    int lane = threadIdx.x & 31;
    int c = lane * 8;

    float acc[8], f[8];
    h8_to_f8(*reinterpret_cast<const uint4*>(h + (size_t)i * HH + c), f);
    float s = snorm[i];
#pragma unroll
    for (int j = 0; j < 8; j++) acc[j] = f[j] * s;

    int p   = rowptr[i];
    int end = rowptr[i + 1];
    for (; p + 3 < end; p += 4) {
        int   r0 = __ldg(&src[p]),     r1 = __ldg(&src[p + 1]);
        int   r2 = __ldg(&src[p + 2]), r3 = __ldg(&src[p + 3]);
        float w0 = __ldg(&wedge[p]),     w1 = __ldg(&wedge[p + 1]);
        float w2 = __ldg(&wedge[p + 2]), w3 = __ldg(&wedge[p + 3]);
        uint4 q0 = *reinterpret_cast<const uint4*>(h + (size_t)r0 * HH + c);
        uint4 q1 = *reinterpret_cast<const uint4*>(h + (size_t)r1 * HH + c);
        uint4 q2 = *reinterpret_cast<const uint4*>(h + (size_t)r2 * HH + c);
        uint4 q3 = *reinterpret_cast<const uint4*>(h + (size_t)r3 * HH + c);
        float f0[8], f1[8], f2[8], f3[8];
        h8_to_f8(q0, f0); h8_to_f8(q1, f1); h8_to_f8(q2, f2); h8_to_f8(q3, f3);
#pragma unroll
        for (int j = 0; j < 8; j++)
            acc[j] += w0 * f0[j] + w1 * f1[j] + w2 * f2[j] + w3 * f3[j];
    }
    for (; p < end; p++) {
        int r = __ldg(&src[p]);
        float wv = __ldg(&wedge[p]);
        float f0[8];
        h8_to_f8(*reinterpret_cast<const uint4*>(h + (size_t)r * HH + c), f0);
#pragma unroll
        for (int j = 0; j < 8; j++) acc[j] += wv * f0[j];
    }

    float o[8];
#pragma unroll
    for (int halfp = 0; halfp < 2; halfp++) {
        int cc = c + halfp * 4;
        float4 B  = *reinterpret_cast<const float4*>(bb + cc);
        float4 G  = *reinterpret_cast<const float4*>(gg + cc);
        float4 BE = *reinterpret_cast<const float4*>(bee + cc);
        float4 M  = *reinterpret_cast<const float4*>(mm + cc);
        float4 V  = *reinterpret_cast<const float4*>(vv + cc);
        float* op = o + halfp * 4;
        float* ap = acc + halfp * 4;
        op[0] = fmaxf((ap[0] + B.x - M.x) * rsqrtf(V.x + BN_EPS) * G.x + BE.x, 0.0f);
        op[1] = fmaxf((ap[1] + B.y - M.y) * rsqrtf(V.y + BN_EPS) * G.y + BE.y, 0.0f);
        op[2] = fmaxf((ap[2] + B.z - M.z) * rsqrtf(V.z + BN_EPS) * G.z + BE.z, 0.0f);
        op[3] = fmaxf((ap[3] + B.w - M.w) * rsqrtf(V.w + BN_EPS) * G.w + BE.w, 0.0f);
    }

    if (!W3MODE) {
        uint32_t hw[4];
#pragma unroll
        for (int j = 0; j < 4; j++) {
            __half2 hp = __floats2half2_rn(o[2 * j], o[2 * j + 1]);
            hw[j] = *reinterpret_cast<uint32_t*>(&hp);
        }
        *reinterpret_cast<uint4*>(hnext + (size_t)i * HH + c) =
            make_uint4(hw[0], hw[1], hw[2], hw[3]);
    } else {
        float p0 = 0.f, p1 = 0.f;
#pragma unroll
        for (int j = 0; j < 8; j++) {
            p0 += o[j] * __ldg(&W3[(c + j) * 2]);
            p1 += o[j] * __ldg(&W3[(c + j) * 2 + 1]);
        }
#pragma unroll
        for (int off = 16; off; off >>= 1) {
            p0 += __shfl_xor_sync(0xFFFFFFFFu, p0, off);
            p1 += __shfl_xor_sync(0xFFFFFFFFu, p1, off);
        }
        if (lane == 0) {
            h3[2 * i]     = p0;
            h3[2 * i + 1] = p1;
        }
    }
}

// -------------------- final gather (OUT=2) --------------------
__global__ void k_gather_out(const float* __restrict__ h3,
                             const int* __restrict__ rowptr, const int* __restrict__ src,
                             const float* __restrict__ wedge, const float* __restrict__ snorm,
                             const float* __restrict__ b3, float* __restrict__ out, int n) {
    int i = blockIdx.x * blockDim.x + threadIdx.x;
    if (i >= n) return;
    float s = snorm[i];
    float a0 = s * h3[2 * i]     + b3[0];
    float a1 = s * h3[2 * i + 1] + b3[1];
    int p = rowptr[i], end = rowptr[i + 1];
    for (; p + 1 < end; p += 2) {
        int   r0 = __ldg(&src[p]),   r1 = __ldg(&src[p + 1]);
        float w0 = __ldg(&wedge[p]), w1 = __ldg(&wedge[p + 1]);
        a0 += w0 * h3[2 * r0]     + w1 * h3[2 * r1];
        a1 += w0 * h3[2 * r0 + 1] + w1 * h3[2 * r1 + 1];
    }
    if (p < end) {
        int r = __ldg(&src[p]);
        float wv = __ldg(&wedge[p]);
        a0 += wv * h3[2 * r];
        a1 += wv * h3[2 * r + 1];
    }
    out[2 * i]     = a0;
    out[2 * i + 1] = a1;
}

// -------------------- launch --------------------
extern "C" void kernel_launch(void* const* d_in, const int* in_sizes, int n_in,
                              void* d_out, int out_size) {
    const float*        x   = (const float*)d_in[0];
    const unsigned int* eiw = (const unsigned int*)d_in[1];
    const float*        w   = (const float*)d_in[2];
    const float*        W1  = (const float*)d_in[3];
    const float*        b1  = (const float*)d_in[4];
    const float*        g1  = (const float*)d_in[5];
    const float*        be1 = (const float*)d_in[6];
    const float*        m1  = (const float*)d_in[7];
    const float*        v1  = (const float*)d_in[8];
    const float*        W2  = (const float*)d_in[9];
    const float*        b2  = (const float*)d_in[10];
    const float*        g2  = (const float*)d_in[11];
    const float*        be2 = (const float*)d_in[12];
    const float*        m2  = (const float*)d_in[13];
    const float*        v2  = (const float*)d_in[14];
    const float*        W3  = (const float*)d_in[15];
    const float*        b3  = (const float*)d_in[16];
    float* out = (float*)d_out;

    int *row, *col, *cnt, *incl, *blksum, *rowptr, *fill, *src;
    float *deg, *dinv, *snorm, *h3, *wedge;
    __half *h16, *hi, *Wh1, *Wh2;
    cudaGetSymbolAddress((void**)&row,    g_row);
    cudaGetSymbolAddress((void**)&col,    g_col);
    cudaGetSymbolAddress((void**)&cnt,    g_cnt);
    cudaGetSymbolAddress((void**)&incl,   g_incl);
    cudaGetSymbolAddress((void**)&blksum, g_blksum);
    cudaGetSymbolAddress((void**)&rowptr, g_rowptr);
    cudaGetSymbolAddress((void**)&fill,   g_fill);
    cudaGetSymbolAddress((void**)&src,    g_src);
    cudaGetSymbolAddress((void**)&wedge,  g_wedge);
    cudaGetSymbolAddress((void**)&deg,    g_deg);
    cudaGetSymbolAddress((void**)&dinv,   g_dinv);
    cudaGetSymbolAddress((void**)&snorm,  g_snorm);
    cudaGetSymbolAddress((void**)&h16,    g_h16);
    cudaGetSymbolAddress((void**)&h3,     g_h3);
    cudaGetSymbolAddress((void**)&hi,     g_hi);
    cudaGetSymbolAddress((void**)&Wh1,    g_Wh1);
    cudaGetSymbolAddress((void**)&Wh2,    g_Wh2);

    static cudaStream_t sB = nullptr;
    static cudaEvent_t  evF = nullptr, evJ = nullptr;
    if (sB == nullptr) {
        cudaStreamCreateWithFlags(&sB, cudaStreamNonBlocking);
        cudaEventCreateWithFlags(&evF, cudaEventDisableTiming);
        cudaEventCreateWithFlags(&evJ, cudaEventDisableTiming);
    }

    const int n = NN, E = EE;
    const int SMEM = 51200;
    cudaFuncSetAttribute(mma_gemm<FIN, true>,
                         cudaFuncAttributeMaxDynamicSharedMemorySize, SMEM);
    cudaFuncSetAttribute(mma_gemm<HH, false>,
                         cudaFuncAttributeMaxDynamicSharedMemorySize, SMEM);

    dim3 t256(256);
    int nb_n  = (n + 255) / 256;
    int nb_e  = (E + 255) / 256;
    int nb_sc = (n + 511) / 512;       // 98
    int nb_g  = n / 8;                 // 6250
    int gemm_grid = (n + 63) / 64;     // 782

    // ---- fork: branch B (graph preproc + W2 transpose) on sB ----
    cudaEventRecord(evF, 0);
    cudaStreamWaitEvent(sB, evF, 0);
    k_preG<<<nb_n, t256, 0, sB>>>(eiw, deg, cnt, fill, n);
    k_extract_deg<<<nb_e, t256, 0, sB>>>(eiw, w, row, col, deg, cnt, E);
    k_scan1<<<nb_sc, 512, 0, sB>>>(cnt, incl, blksum, n);
    k_scan23<<<nb_n, t256, 0, sB>>>(incl, cnt, blksum, rowptr, deg, dinv, snorm, n, E, nb_sc);
    k_norm_fill<<<nb_e, t256, 0, sB>>>(row, col, w, dinv, rowptr, fill, src, wedge, E);
    k_preW2<<<256, t256, 0, sB>>>(W2, Wh2);
    cudaEventRecord(evJ, sB);

    // ---- branch A (W1 + GEMM1) on default stream ----
    k_preW1<<<512, t256>>>(W1, Wh1);
    mma_gemm<FIN, true><<<gemm_grid, t256, SMEM>>>(x, nullptr, Wh1, h16, n);

    // ---- join ----
    cudaStreamWaitEvent(0, evJ, 0);

    // ---- layer 1 gather ----
    k_gather_bn<false><<<nb_g, t256>>>(h16, rowptr, src, wedge, snorm,
                                       b1, g1, be1, m1, v1, hi, nullptr, nullptr, n);

    // ---- layer 2 (A fp16, +W3 fused) ----
    mma_gemm<HH, false><<<gemm_grid, t256, SMEM>>>(nullptr, hi, Wh2, h16, n);
    k_gather_bn<true><<<nb_g, t256>>>(h16, rowptr, src, wedge, snorm,
                                      b2, g2, be2, m2, v2, nullptr, W3, h3, n);

    // ---- layer 3 ----
    k_gather_out<<<nb_n, t256>>>(h3, rowptr, src, wedge, snorm, b3, out, n);
}